// round 9
// baseline (speedup 1.0000x reference)
#include <cuda_runtime.h>
#include <math.h>

#define BATCH 16
#define HH 1024
#define WW 1024
#define PLANE (HH * WW)
#define TX64 64
#define TY32 32
#define NTH  256
#define APB  512            // passA blocks per batch (16 x 32)
#define BTX 64
#define BTY 64

// Blurred grayscale field g [B,H,W]
__device__ float g_buf[BATCH * HH * WW];
__device__ float g_blockmax[BATCH * APB];
__device__ float g_gamma[BATCH];

#define W0f 0.19800304f
#define W1f 0.20099547f
#define W2f 0.20200297f

// ---------------------------------------------------------------------------
// Edge-aware Hessian from 13 register taps (torch.gradient semantics).
// ---------------------------------------------------------------------------
__device__ __forceinline__ void hessian_edge_regs(
    float c00, float u1, float u2, float d1, float d2,
    float l1, float l2, float r1, float r2,
    float ul, float ur, float dl, float dr,
    int gi, int gj, float& h00, float& h01, float& h11)
{
    float gxm, gx0, gxp;
    {
        int gr;
        gr = gi - 1;
        gxm = (gr == 0) ? (c00 - u1)
            : (gi - 1 < 0) ? 0.0f
            : (gr == HH-1) ? (u1 - u2)
            : 0.5f * (c00 - u2);
        gr = gi;
        gx0 = (gr == 0) ? (d1 - c00)
            : (gr == HH-1) ? (c00 - u1)
            : 0.5f * (d1 - u1);
        gr = gi + 1;
        gxp = (gr == 0) ? (d2 - d1)
            : (gr == HH-1) ? (d1 - c00)
            : (gi + 1 > HH-1) ? 0.0f
            : 0.5f * (d2 - c00);
    }
    h00 = (gi == 0) ? (gxp - gx0)
        : (gi == HH-1) ? (gx0 - gxm)
        : 0.5f * (gxp - gxm);

    float gxcm, gxc0, gxcp;
    {
        if (gi == 0) {
            gxcm = dl - l1;
            gxc0 = d1 - c00;
            gxcp = dr - r1;
        } else if (gi == HH-1) {
            gxcm = l1 - ul;
            gxc0 = c00 - u1;
            gxcp = r1 - ur;
        } else {
            gxcm = 0.5f * (dl - ul);
            gxc0 = 0.5f * (d1 - u1);
            gxcp = 0.5f * (dr - ur);
        }
    }
    h01 = (gj == 0) ? (gxcp - gxc0)
        : (gj == WW-1) ? (gxc0 - gxcm)
        : 0.5f * (gxcp - gxcm);

    float gym, gy0, gyp;
    {
        int gc;
        gc = gj - 1;
        gym = (gc == 0) ? (c00 - l1)
            : (gj - 1 < 0) ? 0.0f
            : (gc == WW-1) ? (l1 - l2)
            : 0.5f * (c00 - l2);
        gc = gj;
        gy0 = (gc == 0) ? (r1 - c00)
            : (gc == WW-1) ? (c00 - l1)
            : 0.5f * (r1 - l1);
        gc = gj + 1;
        gyp = (gc == 0) ? (r2 - r1)
            : (gc == WW-1) ? (r1 - c00)
            : (gj + 1 > WW-1) ? 0.0f
            : 0.5f * (r2 - c00);
    }
    h11 = (gj == 0) ? (gyp - gy0)
        : (gj == WW-1) ? (gy0 - gym)
        : 0.5f * (gyp - gym);
}

__device__ __forceinline__ float s_of(float h00, float h01, float h11) {
    float mean = 0.5f * (h00 + h11);
    float dif  = 0.5f * (h00 - h11);
    float disc = sqrtf(dif * dif + h01 * h01);
    float e0 = mean - disc, e1 = mean + disc;
    return sqrtf(e0 * e0 + e1 * e1);
}

__device__ __forceinline__ float response_of(float h00, float h01, float h11, float sinv) {
    float mean = 0.5f * (h00 + h11);
    float dif  = 0.5f * (h00 - h11);
    float disc = sqrtf(dif * dif + h01 * h01);
    float e0 = mean - disc, e1 = mean + disc;
    bool swap = fabsf(e1) < fabsf(e0);
    float lam1 = swap ? e1 : e0;
    float lam2 = fmaxf(swap ? e0 : e1, 1e-10f);
    float rb = __fdividef(fabsf(lam1), lam2);
    float s  = sqrtf(e0 * e0 + e1 * e1);
    float vals = __expf(-2.0f * rb * rb);
    vals *= (1.0f - __expf(s * s * sinv));
    float f = fmaxf(0.0f, vals);
    return (f <= 0.0f) ? 1.0f : f;
}

// ---------------------------------------------------------------------------
// PassA: gray -> separable blur (smem, f4) -> write g (f4) -> Hessian -> s-max
// Tile 64x32, halo 4. SA: gray 40x72, later reused as Gg 36x68. SB: Hh 40x68.
// ---------------------------------------------------------------------------
__global__ __launch_bounds__(NTH) void passA_kernel(const float* __restrict__ x,
                                                    const float* __restrict__ to_gray) {
    __shared__ __align__(16) float SA[40 * 72];
    __shared__ __align__(16) float SB[40 * 68];
    __shared__ float red[NTH / 32];

    const int b  = blockIdx.z;
    const int bx = blockIdx.x * TX64;
    const int by = blockIdx.y * TY32;
    const int tid = threadIdx.x;

    const float c0 = to_gray[0], c1 = to_gray[1], c2 = to_gray[2];
    const float* xb = x + (size_t)b * 3 * PLANE;

    // ---- gray tile: rows by-4..by+35 (40), cols bx-4..bx+67 (18 f4) ----
    {
        int r = tid / 18, c4 = tid % 18;
        for (int idx = tid; idx < 720; idx += NTH) {
            int gi = by + r - 4;
            int gj = bx + c4 * 4 - 4;
            float4 v = make_float4(0.f, 0.f, 0.f, 0.f);
            if (gi >= 0 && gi < HH && gj >= 0 && gj <= WW - 4) {
                size_t off = (size_t)gi * WW + gj;
                float4 p0 = *reinterpret_cast<const float4*>(xb + off);
                float4 p1 = *reinterpret_cast<const float4*>(xb + off + PLANE);
                float4 p2 = *reinterpret_cast<const float4*>(xb + off + 2 * PLANE);
                v.x = c0 * p0.x + c1 * p1.x + c2 * p2.x;
                v.y = c0 * p0.y + c1 * p1.y + c2 * p2.y;
                v.z = c0 * p0.z + c1 * p1.z + c2 * p2.z;
                v.w = c0 * p0.w + c1 * p1.w + c2 * p2.w;
            }
            *reinterpret_cast<float4*>(&SA[r * 72 + c4 * 4]) = v;
            r += 14; c4 += 4; if (c4 >= 18) { c4 -= 18; ++r; }
        }
    }
    __syncthreads();

    // ---- horizontal blur: 40 rows x 17 f4 (cols bx-2..bx+65) ----
    {
        int r = tid / 17, c4 = tid % 17;
        for (int idx = tid; idx < 680; idx += NTH) {
            const float* p = &SA[r * 72 + c4 * 4];
            float4 qa = *reinterpret_cast<const float4*>(p);
            float4 qb = *reinterpret_cast<const float4*>(p + 4);
            float q[8] = {qa.x, qa.y, qa.z, qa.w, qb.x, qb.y, qb.z, qb.w};
            float4 o;
            o.x = W0f*q[0] + W1f*q[1] + W2f*q[2] + W1f*q[3] + W0f*q[4];
            o.y = W0f*q[1] + W1f*q[2] + W2f*q[3] + W1f*q[4] + W0f*q[5];
            o.z = W0f*q[2] + W1f*q[3] + W2f*q[4] + W1f*q[5] + W0f*q[6];
            o.w = W0f*q[3] + W1f*q[4] + W2f*q[5] + W1f*q[6] + W0f*q[7];
            *reinterpret_cast<float4*>(&SB[r * 68 + c4 * 4]) = o;
            r += 15; c4 += 1; if (c4 >= 17) { c4 -= 17; ++r; }
        }
    }
    __syncthreads();

    // ---- vertical blur: 36 rows x 17 f4 into SA (Gg, stride 68) ----
    {
        int r = tid / 17, c4 = tid % 17;
        for (int idx = tid; idx < 612; idx += NTH) {
            const float* p = &SB[r * 68 + c4 * 4];
            float4 a0 = *reinterpret_cast<const float4*>(p);
            float4 a1 = *reinterpret_cast<const float4*>(p + 68);
            float4 a2 = *reinterpret_cast<const float4*>(p + 136);
            float4 a3 = *reinterpret_cast<const float4*>(p + 204);
            float4 a4 = *reinterpret_cast<const float4*>(p + 272);
            float4 o;
            o.x = W0f*a0.x + W1f*a1.x + W2f*a2.x + W1f*a3.x + W0f*a4.x;
            o.y = W0f*a0.y + W1f*a1.y + W2f*a2.y + W1f*a3.y + W0f*a4.y;
            o.z = W0f*a0.z + W1f*a1.z + W2f*a2.z + W1f*a3.z + W0f*a4.z;
            o.w = W0f*a0.w + W1f*a1.w + W2f*a2.w + W1f*a3.w + W0f*a4.w;
            *reinterpret_cast<float4*>(&SA[r * 68 + c4 * 4]) = o;
            r += 15; c4 += 1; if (c4 >= 17) { c4 -= 17; ++r; }
        }
    }
    __syncthreads();

    // ---- tail: write g (f4) + Hessian + s, per-block max ----
    const bool edge = (bx == 0) || (by == 0) || (bx + TX64 == WW) || (by + TY32 == HH);
    const int tx = tid & 15;
    const int ty = tid >> 4;
    float smax = 0.0f;
    float* gb = g_buf + (size_t)b * PLANE;

    #pragma unroll
    for (int k = 0; k < 2; k++) {
        const int row = ty + 16 * k;
        const int gi = by + row;
        const int c0i = tx * 4;
        const float* Rc = &SA[(row + 2) * 68 + c0i];

        float4 A0 = *reinterpret_cast<const float4*>(Rc);
        float4 A1 = *reinterpret_cast<const float4*>(Rc + 4);
        float a[8] = {A0.x, A0.y, A0.z, A0.w, A1.x, A1.y, A1.z, A1.w};

        *reinterpret_cast<float4*>(gb + (size_t)gi * WW + bx + c0i) =
            make_float4(a[2], a[3], a[4], a[5]);

        if (!edge) {
            const float* Ru = Rc - 68;
            const float* Rd = Rc + 68;
            const float* Rt = Rc - 136;
            const float* Rb2 = Rc + 136;
            float4 U0 = *reinterpret_cast<const float4*>(Ru);
            float4 U1 = *reinterpret_cast<const float4*>(Ru + 4);
            float4 D0 = *reinterpret_cast<const float4*>(Rd);
            float4 D1 = *reinterpret_cast<const float4*>(Rd + 4);
            float4 T0 = *reinterpret_cast<const float4*>(Rt);
            float4 T1 = *reinterpret_cast<const float4*>(Rt + 4);
            float4 B0 = *reinterpret_cast<const float4*>(Rb2);
            float4 B1 = *reinterpret_cast<const float4*>(Rb2 + 4);
            float u[8] = {U0.x, U0.y, U0.z, U0.w, U1.x, U1.y, U1.z, U1.w};
            float d[8] = {D0.x, D0.y, D0.z, D0.w, D1.x, D1.y, D1.z, D1.w};
            float t[8] = {T0.x, T0.y, T0.z, T0.w, T1.x, T1.y, T1.z, T1.w};
            float bb[8] = {B0.x, B0.y, B0.z, B0.w, B1.x, B1.y, B1.z, B1.w};

            #pragma unroll
            for (int l = 0; l < 4; l++) {
                float c00 = a[2 + l];
                float A = bb[2 + l] - c00;
                float B = c00 - t[2 + l];
                float h00 = 0.25f * (A - B);
                float C = a[4 + l] - c00;
                float D = c00 - a[l];
                float h11 = 0.25f * (C - D);
                float P = d[3 + l] - u[3 + l];
                float Q = d[1 + l] - u[1 + l];
                float h01 = 0.25f * (P - Q);
                smax = fmaxf(smax, s_of(h00, h01, h11));
            }
        } else {
            #pragma unroll
            for (int l = 0; l < 4; l++) {
                const int gj = bx + c0i + l;
                const float* p = &SA[(row + 2) * 68 + (c0i + l + 2)];
                float h00, h01, h11;
                hessian_edge_regs(p[0], p[-68], p[-136], p[68], p[136],
                                  p[-1], p[-2], p[1], p[2],
                                  p[-69], p[-67], p[67], p[69],
                                  gi, gj, h00, h01, h11);
                smax = fmaxf(smax, s_of(h00, h01, h11));
            }
        }
    }

    #pragma unroll
    for (int off = 16; off > 0; off >>= 1)
        smax = fmaxf(smax, __shfl_xor_sync(0xffffffffu, smax, off));
    if ((tid & 31) == 0) red[tid >> 5] = smax;
    __syncthreads();
    if (tid == 0) {
        float m = red[0];
        #pragma unroll
        for (int i = 1; i < NTH / 32; i++) m = fmaxf(m, red[i]);
        g_blockmax[b * APB + blockIdx.y * gridDim.x + blockIdx.x] = m;
    }
}

// ---------------------------------------------------------------------------
// Gamma: one block, warp w reduces batch w's 512 block maxima
// ---------------------------------------------------------------------------
__global__ void gamma_kernel() {
    const int tid = threadIdx.x;
    const int w = tid >> 5, lane = tid & 31;
    __shared__ float bm[16];

    float m = 0.0f;
    for (int k = lane; k < APB; k += 32) m = fmaxf(m, g_blockmax[w * APB + k]);
    #pragma unroll
    for (int off = 16; off > 0; off >>= 1)
        m = fmaxf(m, __shfl_xor_sync(0xffffffffu, m, off));
    if (lane == 0) bm[w] = m;
    __syncthreads();
    if (tid < 32) {
        float v = (tid < BATCH) ? bm[tid] : 0.0f;
        unsigned any = __ballot_sync(0xffffffffu, (tid < BATCH) && (v != 0.0f));
        if (tid < BATCH) g_gamma[tid] = (any == 0u) ? 1.0f : 0.5f * v;
    }
}

// ---------------------------------------------------------------------------
// PassB: 4-row register strips. Tile 64x64, 256 threads, 16 px/thread.
// Interior: 20 LDG.128 per 16 px, all taps register-resident.
// ---------------------------------------------------------------------------
__global__ __launch_bounds__(NTH) void passB_kernel(float* __restrict__ out) {
    const int b  = blockIdx.z;
    const int bx = blockIdx.x * BTX;
    const int by = blockIdx.y * BTY;
    const int tid = threadIdx.x;
    const int tx = tid & 15;
    const int ty = tid >> 4;
    const int gj0 = bx + tx * 4;
    const int r0  = by + ty * 4;

    const float* gb = g_buf + (size_t)b * PLANE;
    float* ob = out + (size_t)b * PLANE;
    const float gamma = g_gamma[b];
    const float sinv = -1.0f / (2.0f * gamma * gamma);
    const bool edge = (bx == 0) || (by == 0) || (bx + BTX == WW) || (by + BTY == HH);

    if (!edge) {
        const float* base = gb + (size_t)r0 * WW + gj0;
        float4 C[8], L[6], R[6];
        #pragma unroll
        for (int j = 0; j < 8; j++)
            C[j] = __ldg(reinterpret_cast<const float4*>(base + (j - 2) * WW));
        #pragma unroll
        for (int j = 0; j < 6; j++) {
            L[j] = __ldg(reinterpret_cast<const float4*>(base + (j - 1) * WW - 4));
            R[j] = __ldg(reinterpret_cast<const float4*>(base + (j - 1) * WW + 4));
        }
        const float* Cf = reinterpret_cast<const float*>(C);
        const float* Lf = reinterpret_cast<const float*>(L);
        const float* Rf = reinterpret_cast<const float*>(R);

        #pragma unroll
        for (int i = 0; i < 4; i++) {
            // row coverage: C[j] = row r0+j-2; L/R[j] = row r0+j-1
            float q[8];   // cols gj0-2 .. gj0+5, row r0+i
            q[0] = Lf[(i + 1) * 4 + 2]; q[1] = Lf[(i + 1) * 4 + 3];
            #pragma unroll
            for (int m = 0; m < 4; m++) q[2 + m] = Cf[(i + 2) * 4 + m];
            q[6] = Rf[(i + 1) * 4 + 0]; q[7] = Rf[(i + 1) * 4 + 1];

            float ue[6], de[6];  // cols gj0-1 .. gj0+4, rows r0+i-1 / r0+i+1
            ue[0] = Lf[i * 4 + 3];       de[0] = Lf[(i + 2) * 4 + 3];
            #pragma unroll
            for (int m = 0; m < 4; m++) {
                ue[1 + m] = Cf[(i + 1) * 4 + m];
                de[1 + m] = Cf[(i + 3) * 4 + m];
            }
            ue[5] = Rf[i * 4 + 0];       de[5] = Rf[(i + 2) * 4 + 0];

            float4 o; float* op = &o.x;
            #pragma unroll
            for (int m = 0; m < 4; m++) {
                float c00 = q[m + 2];
                float A = Cf[(i + 4) * 4 + m] - c00;   // G(2,0)-G(0,0)
                float B = c00 - Cf[i * 4 + m];         // G(0,0)-G(-2,0)
                float h00 = 0.25f * (A - B);
                float Cc = q[m + 4] - c00;
                float D  = c00 - q[m];
                float h11 = 0.25f * (Cc - D);
                float P = de[m + 2] - ue[m + 2];       // G(1,1)-G(-1,1)
                float Q = de[m] - ue[m];               // G(1,-1)-G(-1,-1)
                float h01 = 0.25f * (P - Q);
                op[m] = response_of(h00, h01, h11, sinv);
            }
            *reinterpret_cast<float4*>(ob + (size_t)(r0 + i) * WW + gj0) = o;
        }
    } else {
        for (int i = 0; i < 4; i++) {
            const int gi = r0 + i;
            float4 o; float* op = &o.x;
            #pragma unroll
            for (int l = 0; l < 4; l++) {
                const int gj = gj0 + l;
                #define CL(v, lim) ((v) < 0 ? 0 : ((v) > (lim) ? (lim) : (v)))
                #define TAP(di, dj) __ldg(gb + (size_t)CL(gi + (di), HH-1) * WW + CL(gj + (dj), WW-1))
                float c00 = TAP(0,0);
                float u1 = TAP(-1,0), u2 = TAP(-2,0), d1 = TAP(1,0), d2 = TAP(2,0);
                float l1 = TAP(0,-1), l2 = TAP(0,-2), r1 = TAP(0,1), r2 = TAP(0,2);
                float ul = TAP(-1,-1), ur = TAP(-1,1), dl = TAP(1,-1), dr = TAP(1,1);
                #undef TAP
                #undef CL
                float h00, h01, h11;
                hessian_edge_regs(c00, u1, u2, d1, d2, l1, l2, r1, r2,
                                  ul, ur, dl, dr, gi, gj, h00, h01, h11);
                op[l] = response_of(h00, h01, h11, sinv);
            }
            *reinterpret_cast<float4*>(ob + (size_t)gi * WW + gj0) = o;
        }
    }
}

extern "C" void kernel_launch(void* const* d_in, const int* in_sizes, int n_in,
                              void* d_out, int out_size) {
    const float* x       = (const float*)d_in[0];
    const float* to_gray = (const float*)d_in[1];
    float* out = (float*)d_out;

    dim3 blockA(NTH);
    dim3 gridA(WW / TX64, HH / TY32, BATCH);
    dim3 blockB(NTH);
    dim3 gridB(WW / BTX, HH / BTY, BATCH);

    passA_kernel<<<gridA, blockA>>>(x, to_gray);
    gamma_kernel<<<1, 512>>>();
    passB_kernel<<<gridB, blockB>>>(out);
}